// round 10
// baseline (speedup 1.0000x reference)
#include <cuda_runtime.h>
#include <cstdint>

// B=4, H=512, W=512, K=8, BKG_DEPTH=100
// Inputs: colors f32[B,H,W,8,4], zbuf f32[B,H,W,8], labels i32[B,H,W,8], bg f32[3]
// Output (flat f32): image[NPIX*4] | depth[NPIX] | label[NPIX] | human[NPIX*8*4]

constexpr int   NPIX      = 4 * 512 * 512;     // 1,048,576
constexpr float BKG_DEPTH = 100.0f;

constexpr long long IMG_OFF   = 0;
constexpr long long DEPTH_OFF = (long long)NPIX * 4;
constexpr long long LABEL_OFF = DEPTH_OFF + NPIX;
constexpr long long HUMAN_OFF = LABEL_OFF + NPIX;

constexpr int BLOCK  = 128;                    // threads == pixels per tile
constexpr int NTILES = NPIX / BLOCK;           // 8192
constexpr int CTAS   = 152 * 6;                // 912 persistent CTAs (6/SM)

// dynamic smem: sbuf[2][BLOCK*8] float4 (32 KB) + stab[BLOCK] unsigned (0.5 KB)
constexpr size_t SMEM_BYTES = (size_t)2 * BLOCK * 8 * sizeof(float4)
                            + (size_t)BLOCK * sizeof(unsigned);

extern __shared__ float4 smem_dyn[];

__global__ void __launch_bounds__(BLOCK, 6)
alpha_composite_kernel(const float4* __restrict__ colors,   // [NPIX*8] float4
                       const float4* __restrict__ zbuf4,    // [NPIX*2] float4
                       const int4*   __restrict__ labl4,    // [NPIX*2] int4
                       const float*  __restrict__ bg,       // [3]
                       float*        __restrict__ out)
{
    float4*   sbufA = smem_dyn;                 // two 16 KB tile buffers
    float4*   sbufB = smem_dyn + BLOCK * 8;
    unsigned* stab  = reinterpret_cast<unsigned*>(smem_dyn + BLOCK * 16);

    const int tid = threadIdx.x;
    const float bgr = __ldg(bg + 0);
    const float bgg = __ldg(bg + 1);
    const float bgb = __ldg(bg + 2);

    // XOR-swizzled slot(q,j) = q*8 + (j^(q&7)): conflict-free for both the
    // coalesced fill/drain and the per-pixel strided access.
    auto prefetch_colors = [&](int t, float4* buf) {
        const long long fbase = (long long)t * BLOCK * 8;   // float4 units
#pragma unroll
        for (int it = 0; it < 8; ++it) {
            const int idx = it * BLOCK + tid;               // coalesced
            const int q = idx >> 3, j = idx & 7;
            const uint32_t saddr =
                (uint32_t)__cvta_generic_to_shared(&buf[q * 8 + (j ^ (q & 7))]);
            const float4* g = colors + fbase + idx;
            asm volatile("cp.async.cg.shared.global [%0], [%1], 16;\n"
                         :: "r"(saddr), "l"(g));
        }
    };

    int t = blockIdx.x;                                     // first tile

    // ---- prologue: stage tile t (colors -> smem, z/labels -> registers) ----
    if (t < NTILES) prefetch_colors(t, sbufA);
    asm volatile("cp.async.commit_group;\n");

    float4 zn0, zn1; int4 ln0, ln1;
    if (t < NTILES) {
        const long long pp = (long long)t * BLOCK + tid;
        zn0 = zbuf4[pp * 2 + 0]; zn1 = zbuf4[pp * 2 + 1];
        ln0 = labl4[pp * 2 + 0]; ln1 = labl4[pp * 2 + 1];
    }

    int cur = 0;
    for (; t < NTILES; t += CTAS) {
        float4* bufc = cur ? sbufB : sbufA;
        float4* bufn = cur ? sbufA : sbufB;
        const int tn = t + CTAS;

        // ---- prefetch next tile while we process the current one ----
        if (tn < NTILES) prefetch_colors(tn, bufn);
        asm volatile("cp.async.commit_group;\n");           // uniform group count

        const float zz[8] = { zn0.x, zn0.y, zn0.z, zn0.w,
                              zn1.x, zn1.y, zn1.z, zn1.w };
        const unsigned Lpack =
            ((unsigned)ln0.x      ) | ((unsigned)ln0.y <<  4) |
            ((unsigned)ln0.z <<  8) | ((unsigned)ln0.w << 12) |
            ((unsigned)ln1.x << 16) | ((unsigned)ln1.y << 20) |
            ((unsigned)ln1.z << 24) | ((unsigned)ln1.w << 28);

        if (tn < NTILES) {
            const long long pp = (long long)tn * BLOCK + tid;
            zn0 = zbuf4[pp * 2 + 0]; zn1 = zbuf4[pp * 2 + 1];
            ln0 = labl4[pp * 2 + 0]; ln1 = labl4[pp * 2 + 1];
        }

        // current tile's group was committed a full iteration ago -> short wait
        asm volatile("cp.async.wait_group 1;\n");
        __syncthreads();

        // ---- fused back-to-front scan + human blend (in-place overwrite) ----
        const long long p     = (long long)t * BLOCK + tid;
        const long long fbase = (long long)t * BLOCK * 8;

        float r = bgr, g = bgg, b = bgb;
        float a = 0.0f;
        float d = BKG_DEPTH;
        float labv = -1.0f;          // miss sentinel -> output -1 directly
        unsigned T = 0xFFFFFFFFu;    // 8 nibbles, 0xF = miss

#pragma unroll
        for (int k = 7; k >= 0; --k) {
            const int slot = tid * 8 + (k ^ (tid & 7));
            const float4 c = bufc[slot];
            const float al = c.w;
            const float om = 1.0f - al;
            const unsigned lk = (Lpack >> (4 * k)) & 7u;

            r = c.x * al + r * om;
            g = c.y * al + g * om;
            b = c.z * al + b * om;
            a = fmaxf(al, a);

            const bool znn = !(zz[k] < 0.0f);       // reference NaN handling
            if (zz[k] > 0.0f)     d    = zz[k] * al + d * om;
            if (znn && al > 0.5f) labv = (float)lk;

            bufc[slot] = make_float4(c.x * al + bgr * om,   // human blend
                                     c.y * al + bgg * om,
                                     c.z * al + bgb * om,
                                     al);

            if (znn)                                 // descending k: first k wins
                T = (T & ~(0xFu << (4 * lk))) | ((unsigned)k << (4 * lk));
        }
        stab[tid] = T;

        reinterpret_cast<float4*>(out + IMG_OFF)[p] = make_float4(r, g, b, a);
        out[DEPTH_OFF + p] = d;
        out[LABEL_OFF + p] = labv;

        __syncthreads();

        // ---- coalesced drain of human images via nibble-table gather ----
        {
            float4* ho = reinterpret_cast<float4*>(out + HUMAN_OFF);
#pragma unroll
            for (int it = 0; it < 8; ++it) {
                const int idx = it * BLOCK + tid;          // coalesced
                const int q = idx >> 3, n = idx & 7;       // pixel q, label n
                const unsigned kk = (stab[q] >> (4 * n)) & 0xFu;
                float4 v;
                if (kk < 8u) v = bufc[q * 8 + ((int)kk ^ (q & 7))];
                else         v = make_float4(bgr, bgg, bgb, 0.0f);
                ho[fbase + idx] = v;
            }
        }
        __syncthreads();    // bufc fully drained before next prefetch reuses it
        cur ^= 1;
    }
}

extern "C" void kernel_launch(void* const* d_in, const int* in_sizes, int n_in,
                              void* d_out, int out_size)
{
    const float4* colors = (const float4*)d_in[0];
    const float4* zbuf4  = (const float4*)d_in[1];
    const int4*   labl4  = (const int4*)d_in[2];
    const float*  bg     = (const float*)d_in[3];
    float*        out    = (float*)d_out;

    cudaFuncSetAttribute(alpha_composite_kernel,
                         cudaFuncAttributeMaxDynamicSharedMemorySize,
                         (int)SMEM_BYTES);

    alpha_composite_kernel<<<CTAS, BLOCK, SMEM_BYTES>>>(colors, zbuf4, labl4, bg, out);
}

// round 11
// speedup vs baseline: 1.1148x; 1.1148x over previous
#include <cuda_runtime.h>
#include <cstdint>

// B=4, H=512, W=512, K=8, BKG_DEPTH=100
// Inputs: colors f32[B,H,W,8,4], zbuf f32[B,H,W,8], labels i32[B,H,W,8], bg f32[3]
// Output (flat f32): image[NPIX*4] | depth[NPIX] | label[NPIX] | human[NPIX*8*4]

constexpr int   NPIX      = 4 * 512 * 512;     // 1,048,576
constexpr float BKG_DEPTH = 100.0f;

constexpr long long IMG_OFF   = 0;
constexpr long long DEPTH_OFF = (long long)NPIX * 4;
constexpr long long LABEL_OFF = DEPTH_OFF + NPIX;
constexpr long long HUMAN_OFF = LABEL_OFF + NPIX;

constexpr int BLOCK = 128;                     // threads == pixels per tile

__global__ void __launch_bounds__(BLOCK, 10)   // reg cap 51 -> ~10 CTAs/SM
alpha_composite_kernel(const float4* __restrict__ colors,   // [NPIX*8] float4
                       const float4* __restrict__ zbuf4,    // [NPIX*2] float4
                       const int4*   __restrict__ labl4,    // [NPIX*2] int4
                       const float*  __restrict__ bg,       // [3]
                       float*        __restrict__ out)
{
    // 16 KB staging buffer, XOR-swizzled: slot(q,j) = q*8 + (j^(q&7)).
    // Conflict-free for both coalesced fill/drain and per-pixel strided access.
    __shared__ float4 sbuf[BLOCK * 8];
    // Per-pixel nibble table: nibble n = first layer k with label n (0xF = miss)
    __shared__ unsigned stab[BLOCK];

    const int tid = threadIdx.x;
    const long long p     = (long long)blockIdx.x * BLOCK + tid;
    const long long fbase = (long long)blockIdx.x * BLOCK * 8;   // float4 units

    // ---- Phase 1: cp.async color fill (no register staging, L2-streaming) ----
#pragma unroll
    for (int it = 0; it < 8; ++it) {
        const int idx = it * BLOCK + tid;              // coalesced
        const int q = idx >> 3, j = idx & 7;
        const uint32_t saddr =
            (uint32_t)__cvta_generic_to_shared(&sbuf[q * 8 + (j ^ (q & 7))]);
        const float4* gptr = colors + fbase + idx;
        asm volatile("cp.async.cg.shared.global [%0], [%1], 16;\n"
                     :: "r"(saddr), "l"(gptr));
    }
    asm volatile("cp.async.commit_group;\n");

    // Overlap: z / labels / bg loads while cp.async is in flight
    const float4 z0 = zbuf4[p * 2 + 0];
    const float4 z1 = zbuf4[p * 2 + 1];
    const int4   l0 = labl4[p * 2 + 0];
    const int4   l1 = labl4[p * 2 + 1];
    const float bgr = __ldg(bg + 0);
    const float bgg = __ldg(bg + 1);
    const float bgb = __ldg(bg + 2);

    const float zz[8] = { z0.x, z0.y, z0.z, z0.w, z1.x, z1.y, z1.z, z1.w };
    // Pack 8 labels (each in [0,8)) into one nibble word: saves 7 live regs.
    const unsigned Lpack =
        ((unsigned)l0.x      ) | ((unsigned)l0.y <<  4) |
        ((unsigned)l0.z <<  8) | ((unsigned)l0.w << 12) |
        ((unsigned)l1.x << 16) | ((unsigned)l1.y << 20) |
        ((unsigned)l1.z << 24) | ((unsigned)l1.w << 28);

    asm volatile("cp.async.wait_group 0;\n");
    __syncthreads();

    // ---- Phase 2: fused back-to-front scan + human blend (in-place) ----
    float r = bgr, g = bgg, b = bgb;
    float a = 0.0f;
    float d = BKG_DEPTH;
    float labv = -1.0f;          // miss sentinel -> output -1 directly
    unsigned T = 0xFFFFFFFFu;    // 8 nibbles, 0xF = miss

#pragma unroll
    for (int k = 7; k >= 0; --k) {
        const int slot = tid * 8 + (k ^ (tid & 7));
        const float4 c = sbuf[slot];
        const float al = c.w;
        const float om = 1.0f - al;
        const unsigned lk = (Lpack >> (4 * k)) & 7u;

        r = c.x * al + r * om;
        g = c.y * al + g * om;
        b = c.z * al + b * om;
        a = fmaxf(al, a);

        const bool znn = !(zz[k] < 0.0f);          // reference NaN handling
        if (zz[k] > 0.0f)     d    = zz[k] * al + d * om;
        if (znn && al > 0.5f) labv = (float)lk;

        // human blend overwrites the color slot (this thread is sole owner)
        sbuf[slot] = make_float4(c.x * al + bgr * om,
                                 c.y * al + bgg * om,
                                 c.z * al + bgb * om,
                                 al);

        if (znn)                                    // descending k: first k wins
            T = (T & ~(0xFu << (4 * lk))) | ((unsigned)k << (4 * lk));
    }
    stab[tid] = T;

    reinterpret_cast<float4*>(out + IMG_OFF)[p] = make_float4(r, g, b, a);
    out[DEPTH_OFF + p] = d;
    out[LABEL_OFF + p] = labv;

    __syncthreads();

    // ---- Phase 3: coalesced drain of human images via nibble-table gather ----
    {
        float4* ho = reinterpret_cast<float4*>(out + HUMAN_OFF);
#pragma unroll
        for (int it = 0; it < 8; ++it) {
            const int idx = it * BLOCK + tid;              // coalesced
            const int q = idx >> 3, n = idx & 7;           // pixel q, label n
            const unsigned kk = (stab[q] >> (4 * n)) & 0xFu;
            float4 v;
            if (kk < 8u) v = sbuf[q * 8 + ((int)kk ^ (q & 7))];
            else         v = make_float4(bgr, bgg, bgb, 0.0f);  // miss -> (bg,0)
            ho[fbase + idx] = v;
        }
    }
}

extern "C" void kernel_launch(void* const* d_in, const int* in_sizes, int n_in,
                              void* d_out, int out_size)
{
    const float4* colors = (const float4*)d_in[0];
    const float4* zbuf4  = (const float4*)d_in[1];
    const int4*   labl4  = (const int4*)d_in[2];
    const float*  bg     = (const float*)d_in[3];
    float*        out    = (float*)d_out;

    alpha_composite_kernel<<<NPIX / BLOCK, BLOCK>>>(colors, zbuf4, labl4, bg, out);
}